// round 6
// baseline (speedup 1.0000x reference)
#include <cuda_runtime.h>
#include <cuda_fp16.h>
#include <cstdint>

// ---------------------------------------------------------------------------
// EdgeDense: z = x @ W + b  (N x 32, stored fp16), then
//            out[e] = w_e * (z[rows[e]] + z[cols[e]])   (fp32 out)
// N_NODES = 100000, IN = 128, OUT = 32, E = 1.6M
// ---------------------------------------------------------------------------

#define MAX_NODES 100000
#define IN_F 128
#define OUT_F 32

#define GEMM_BLOCK 256          // threads per block
#define NPB 256                 // nodes per block
#define CHUNK_K 16              // k-values staged per chunk
#define SX_STRIDE 260           // 256 nodes + 4 pad (16B-aligned float4 rows)

// z in fp16: 100000 * 32 * 2B = 6.4 MB (L2-resident). Device global.
__device__ __half2 g_zh[(size_t)MAX_NODES * (OUT_F / 2)];
// Index-dtype flag: 1 => indices are int64, 0 => indices are int32.
__device__ int g_idx64;

typedef unsigned long long ull_t;

#define FMA_F32X2(d, a, b, c) \
    asm("fma.rn.f32x2 %0, %1, %2, %3;" : "=l"(d) : "l"(a), "l"(b), "l"(c))
#define PACK_DUP_F32X2(d, s) \
    asm("mov.b64 %0, {%1, %2};" : "=l"(d) : "f"(s), "f"(s))
#define UNPACK_F32X2(lo, hi, in) \
    asm("mov.b64 {%0, %1}, %2;" : "=f"(lo), "=f"(hi) : "l"(in))

// ---------------------------------------------------------------------------
// GEMM, outer-product register tile: thread (ng, oq) computes 8 nodes
// (ng*8..ng*8+7) x 4 outputs (oq*4..oq*4+3) as 16 f32x2 accumulators.
// Per k: 1 broadcast W-LDS.128 + 2 x-LDS.128 feed 16 FMA2 (was 8 W-LDS per
// 32 FMA2) -- LDS issue drops ~4x, FMA floor is the binder.
// x is staged TRANSPOSED, sx[k][node], so 8 consecutive nodes for fixed k
// are one conflict-free float4 pair. Block 0 also classifies the edge-index
// dtype (JAX x64-off hazard): int32 data read as int64 words is >= 2^32
// whenever the odd word != 0 -- unambiguous over 256 words for uniform
// indices in [0, 100000).
// ---------------------------------------------------------------------------
__global__ __launch_bounds__(GEMM_BLOCK)
void gemm_kernel(const float4* __restrict__ x4,
                 const float*  __restrict__ W,    // [128][32] row-major
                 const float*  __restrict__ b,    // [32]
                 __half2* __restrict__ zh,
                 int n_nodes,
                 const long long* __restrict__ idx_probe) {
    __shared__ float sW[IN_F * OUT_F];            // 16 KB
    __shared__ float sx[CHUNK_K * SX_STRIDE];     // 16.6 KB
    __shared__ int s_bad;

    int tid = threadIdx.x;
    int ng = tid >> 3;          // node group 0..31 (8 nodes each)
    int oq = tid & 7;           // output quad 0..7
    int base = blockIdx.x * NPB;

    #pragma unroll
    for (int i = tid; i < IN_F * OUT_F; i += GEMM_BLOCK) sW[i] = W[i];
    if (blockIdx.x == 0 && tid == 0) s_bad = 0;

    if (blockIdx.x == 0) {
        long long v = idx_probe[tid];
        if (v < 0 || v >= (long long)n_nodes) atomicOr(&s_bad, 1);
    }

    // 8 nodes x 2 f32x2 accumulators, seeded with this quad's bias pairs.
    const ull_t* b2 = (const ull_t*)b;
    ull_t b01 = __ldg(&b2[2 * oq + 0]);
    ull_t b23 = __ldg(&b2[2 * oq + 1]);
    ull_t acc0[8], acc1[8];
    #pragma unroll
    for (int n = 0; n < 8; n++) { acc0[n] = b01; acc1[n] = b23; }

    #pragma unroll
    for (int chunk = 0; chunk < IN_F / CHUNK_K; chunk++) {
        __syncthreads();
        // Stage 256 nodes x 16 k-values, transposed into sx[k][node].
        // Each thread reads 4 float4 (64B node-slices, coalesced-ish) and
        // scatters 16 scalars (2-way bank conflict, negligible volume).
        #pragma unroll
        for (int j = 0; j < 4; j++) {
            int i = j * GEMM_BLOCK + tid;
            int n = i >> 2;                 // node 0..255
            int q = i & 3;                  // float4 index within 16-k slice
            int gn = base + n;
            float4 v = make_float4(0.f, 0.f, 0.f, 0.f);
            if (gn < n_nodes)
                v = __ldg(&x4[(size_t)gn * (IN_F / 4) + chunk * 4 + q]);
            int k0 = q * 4;
            sx[(k0 + 0) * SX_STRIDE + n] = v.x;
            sx[(k0 + 1) * SX_STRIDE + n] = v.y;
            sx[(k0 + 2) * SX_STRIDE + n] = v.z;
            sx[(k0 + 3) * SX_STRIDE + n] = v.w;
        }
        __syncthreads();

        #pragma unroll
        for (int kk = 0; kk < CHUNK_K; kk++) {
            int k = chunk * CHUNK_K + kk;
            // This quad's W pair: 4 consecutive floats = 2 f32x2 operands.
            ulonglong2 wv = *reinterpret_cast<const ulonglong2*>(
                sW + k * OUT_F + oq * 4);
            const float* xp = &sx[kk * SX_STRIDE + ng * 8];
            float4 xa = *reinterpret_cast<const float4*>(xp);
            float4 xb = *reinterpret_cast<const float4*>(xp + 4);
            float xs[8] = {xa.x, xa.y, xa.z, xa.w, xb.x, xb.y, xb.z, xb.w};
            #pragma unroll
            for (int n = 0; n < 8; n++) {
                ull_t ss;
                PACK_DUP_F32X2(ss, xs[n]);
                FMA_F32X2(acc0[n], ss, wv.x, acc0[n]);
                FMA_F32X2(acc1[n], ss, wv.y, acc1[n]);
            }
        }
    }

    // Store: 8 nodes, 8B (4 fp16) each at offset oq*8 in the 64B z row.
    #pragma unroll
    for (int n = 0; n < 8; n++) {
        int node = base + ng * 8 + n;
        if (node >= n_nodes) continue;
        float f0, f1, f2, f3;
        UNPACK_F32X2(f0, f1, acc0[n]);
        UNPACK_F32X2(f2, f3, acc1[n]);
        __half2 h0 = __floats2half2_rn(f0, f1);
        __half2 h1 = __floats2half2_rn(f2, f3);
        uint2 hv;
        hv.x = *reinterpret_cast<unsigned*>(&h0);
        hv.y = *reinterpret_cast<unsigned*>(&h1);
        *reinterpret_cast<uint2*>(
            reinterpret_cast<char*>(zh) + (size_t)node * 64 + oq * 8) = hv;
    }

    if (blockIdx.x == 0) {
        __syncthreads();
        if (tid == 0) g_idx64 = s_bad ? 0 : 1;
    }
}

// ---------------------------------------------------------------------------
// Edge kernel: 16 lanes per edge, 4B (uint = 2 fp16) gathers -- each gather
// warp-instruction touches only 2 distinct z rows (2 lines), shifting L1tex
// wavefronts toward the 1.0 cyc cross-instruction rate (was 4 lines/instr
// at the 2.07 within-instruction replay rate). Gathers use __ldcg: z's L1
// hit rate is ~3.5% (6.4MB vs 228KB), so skipping L1 fill loses nothing.
// 4 edges per thread (m + q*E/4), all loads front-batched. Output: one
// STG.64 per lane per edge, coalesced, streaming.
// ---------------------------------------------------------------------------
__global__ __launch_bounds__(256)
void edge_kernel(const __half2* __restrict__ zh,
                 const int* __restrict__ rows,
                 const int* __restrict__ cols,
                 const float* __restrict__ vals,
                 float2* __restrict__ out,
                 int n_edges) {
    int gid = blockIdx.x * blockDim.x + threadIdx.x;
    int E4 = (n_edges + 3) >> 2;
    int m = gid >> 4;
    int c = gid & 15;
    if (m >= E4) return;

    int sh = g_idx64;           // 0: int32 layout, 1: int64 (read low word)

    int e[4];
    bool has[4];
    #pragma unroll
    for (int q = 0; q < 4; q++) {
        e[q] = m + q * E4;
        has[q] = (e[q] < n_edges);
    }

    int ri[4], ci[4];
    float wv[4];
    #pragma unroll
    for (int q = 0; q < 4; q++) {
        ri[q] = 0; ci[q] = 0; wv[q] = 0.f;
        if (has[q]) {
            ri[q] = __ldcs(&rows[e[q] << sh]);
            ci[q] = __ldcs(&cols[e[q] << sh]);
            wv[q] = __ldcs(&vals[e[q]]);
        }
    }

    const unsigned* zw = reinterpret_cast<const unsigned*>(zh); // 16 per row
    unsigned ga[4], gd[4];
    #pragma unroll
    for (int q = 0; q < 4; q++) {
        ga[q] = 0; gd[q] = 0;
        if (has[q]) {
            ga[q] = __ldcg(&zw[(size_t)ri[q] * 16 + c]);
            gd[q] = __ldcg(&zw[(size_t)ci[q] * 16 + c]);
        }
    }

    #pragma unroll
    for (int q = 0; q < 4; q++) {
        if (!has[q]) continue;
        float2 fa = __half22float2(*reinterpret_cast<__half2*>(&ga[q]));
        float2 fd = __half22float2(*reinterpret_cast<__half2*>(&gd[q]));
        float2 o;
        o.x = wv[q] * (fa.x + fd.x);
        o.y = wv[q] * (fa.y + fd.y);
        __stcs(&out[(size_t)e[q] * 16 + c], o);
    }
}

// ---------------------------------------------------------------------------
// Launch. Inputs (metadata order): x, W, b, edge_rows, edge_cols, edge_vals.
// ---------------------------------------------------------------------------
extern "C" void kernel_launch(void* const* d_in, const int* in_sizes, int n_in,
                              void* d_out, int out_size) {
    const float4* x4   = (const float4*)d_in[0];
    const float*  W    = (const float*)d_in[1];
    const float*  b    = (const float*)d_in[2];
    const void*   rows = d_in[3];
    const void*   cols = d_in[4];
    const float*  vals = (const float*)d_in[5];
    float2* out = (float2*)d_out;

    int n_nodes = in_sizes[0] / IN_F;
    int n_edges = in_sizes[3];

    __half2* zh = nullptr;
    cudaGetSymbolAddress((void**)&zh, g_zh);

    // 1) z = x @ W + b  (+ index-dtype probe in block 0)
    int gemm_blocks = (n_nodes + NPB - 1) / NPB;
    gemm_kernel<<<gemm_blocks, GEMM_BLOCK>>>(
        x4, W, b, zh, n_nodes, (const long long*)rows);

    // 2) out[e] = w_e * (z[r] + z[c]), 4 edges/thread, 16 lanes/edge
    int E4 = (n_edges + 3) >> 2;
    long long total = (long long)E4 * 16;
    int edge_blocks = (int)((total + 255) / 256);
    edge_kernel<<<edge_blocks, 256>>>(zh, (const int*)rows, (const int*)cols,
                                      vals, out, n_edges);
}

// round 7
// speedup vs baseline: 1.1029x; 1.1029x over previous
#include <cuda_runtime.h>
#include <cuda_fp16.h>
#include <cstdint>

// ---------------------------------------------------------------------------
// EdgeDense: z = x @ W + b  (N x 32, stored fp16), then
//            out[e] = w_e * (z[rows[e]] + z[cols[e]])   (fp32 out)
// N_NODES = 100000, IN = 128, OUT = 32, E = 1.6M
// ---------------------------------------------------------------------------

#define MAX_NODES 100000
#define IN_F 128
#define OUT_F 32

#define GEMM_BLOCK 256          // threads per block
#define NPB 256                 // nodes per block
#define CHUNK_K 16              // k-values staged per chunk
#define N_CHUNKS (IN_F / CHUNK_K)
#define SX_STRIDE 260           // 256 nodes + 4 pad (16B-aligned float4 rows)

// z in fp16: 100000 * 32 * 2B = 6.4 MB (L2-resident). Device global.
__device__ __half2 g_zh[(size_t)MAX_NODES * (OUT_F / 2)];
// Index-dtype flag: 1 => indices are int64, 0 => indices are int32.
__device__ int g_idx64;

typedef unsigned long long ull_t;

#define FMA_F32X2(d, a, b, c) \
    asm("fma.rn.f32x2 %0, %1, %2, %3;" : "=l"(d) : "l"(a), "l"(b), "l"(c))
#define PACK_DUP_F32X2(d, s) \
    asm("mov.b64 %0, {%1, %2};" : "=l"(d) : "f"(s), "f"(s))
#define UNPACK_F32X2(lo, hi, in) \
    asm("mov.b64 {%0, %1}, %2;" : "=f"(lo), "=f"(hi) : "l"(in))

// ---------------------------------------------------------------------------
// GEMM, outer-product register tile: thread (ng, oq) computes 8 nodes x 4
// outputs as 16 f32x2 accumulators. Per k: 1 broadcast W-LDS.128 + 2
// x-LDS.128 feed 16 FMA2. FFMA2 is rt~4 on sm_103a (measured) -> FMA floor
// ~21.6us; the remaining overhead is staging latency, attacked here with
// REGISTER DOUBLE-BUFFERING: the global x loads for chunk c+1 are issued
// before the compute of chunk c, hiding LDG latency under 688 FMA2.
// x staged TRANSPOSED sx[k][node]. Block 0 also classifies the edge-index
// dtype (JAX x64-off hazard): int32 read as int64 words is >= 2^32 whenever
// the odd word != 0 -- unambiguous over 256 uniform indices in [0, 100000).
// ---------------------------------------------------------------------------
__global__ __launch_bounds__(GEMM_BLOCK)
void gemm_kernel(const float4* __restrict__ x4,
                 const float*  __restrict__ W,    // [128][32] row-major
                 const float*  __restrict__ b,    // [32]
                 __half2* __restrict__ zh,
                 int n_nodes,
                 const long long* __restrict__ idx_probe) {
    __shared__ float sW[IN_F * OUT_F];            // 16 KB
    __shared__ float sx[CHUNK_K * SX_STRIDE];     // 16.6 KB
    __shared__ int s_bad;

    int tid = threadIdx.x;
    int ng = tid >> 3;          // node group 0..31 (8 nodes each)
    int oq = tid & 7;           // output quad 0..7
    int base = blockIdx.x * NPB;

    #pragma unroll
    for (int i = tid; i < IN_F * OUT_F; i += GEMM_BLOCK) sW[i] = W[i];
    if (blockIdx.x == 0 && tid == 0) s_bad = 0;

    if (blockIdx.x == 0) {
        long long v = idx_probe[tid];
        if (v < 0 || v >= (long long)n_nodes) atomicOr(&s_bad, 1);
    }

    // Staging indices for this thread (fixed across chunks).
    int sn[4], sq[4], sgn[4];
    #pragma unroll
    for (int j = 0; j < 4; j++) {
        int i = j * GEMM_BLOCK + tid;
        sn[j] = i >> 2;                 // node 0..255
        sq[j] = i & 3;                  // float4 index within 16-k slice
        sgn[j] = base + sn[j];
    }

    // Preload chunk 0 into registers.
    float4 ld[4];
    #pragma unroll
    for (int j = 0; j < 4; j++) {
        ld[j] = make_float4(0.f, 0.f, 0.f, 0.f);
        if (sgn[j] < n_nodes)
            ld[j] = __ldg(&x4[(size_t)sgn[j] * (IN_F / 4) + sq[j]]);
    }

    // 8 nodes x 2 f32x2 accumulators, seeded with this quad's bias pairs.
    const ull_t* b2 = (const ull_t*)b;
    ull_t b01 = __ldg(&b2[2 * oq + 0]);
    ull_t b23 = __ldg(&b2[2 * oq + 1]);
    ull_t acc0[8], acc1[8];
    #pragma unroll
    for (int n = 0; n < 8; n++) { acc0[n] = b01; acc1[n] = b23; }

    #pragma unroll
    for (int chunk = 0; chunk < N_CHUNKS; chunk++) {
        // Scatter prefetched registers (transposed) into sx.
        #pragma unroll
        for (int j = 0; j < 4; j++) {
            int k0 = sq[j] * 4;
            int n = sn[j];
            sx[(k0 + 0) * SX_STRIDE + n] = ld[j].x;
            sx[(k0 + 1) * SX_STRIDE + n] = ld[j].y;
            sx[(k0 + 2) * SX_STRIDE + n] = ld[j].z;
            sx[(k0 + 3) * SX_STRIDE + n] = ld[j].w;
        }
        __syncthreads();

        // Issue next chunk's global loads NOW; they complete under compute.
        if (chunk + 1 < N_CHUNKS) {
            #pragma unroll
            for (int j = 0; j < 4; j++) {
                ld[j] = make_float4(0.f, 0.f, 0.f, 0.f);
                if (sgn[j] < n_nodes)
                    ld[j] = __ldg(&x4[(size_t)sgn[j] * (IN_F / 4)
                                      + (chunk + 1) * 4 + sq[j]]);
            }
        }

        #pragma unroll
        for (int kk = 0; kk < CHUNK_K; kk++) {
            int k = chunk * CHUNK_K + kk;
            ulonglong2 wv = *reinterpret_cast<const ulonglong2*>(
                sW + k * OUT_F + oq * 4);
            const float* xp = &sx[kk * SX_STRIDE + ng * 8];
            float4 xa = *reinterpret_cast<const float4*>(xp);
            float4 xb = *reinterpret_cast<const float4*>(xp + 4);
            float xs[8] = {xa.x, xa.y, xa.z, xa.w, xb.x, xb.y, xb.z, xb.w};
            #pragma unroll
            for (int n = 0; n < 8; n++) {
                ull_t ss;
                PACK_DUP_F32X2(ss, xs[n]);
                FMA_F32X2(acc0[n], ss, wv.x, acc0[n]);
                FMA_F32X2(acc1[n], ss, wv.y, acc1[n]);
            }
        }
        __syncthreads();   // compute done before next scatter overwrites sx
    }

    // Store: 8 nodes, 8B (4 fp16) each at offset oq*8 in the 64B z row.
    #pragma unroll
    for (int n = 0; n < 8; n++) {
        int node = base + ng * 8 + n;
        if (node >= n_nodes) continue;
        float f0, f1, f2, f3;
        UNPACK_F32X2(f0, f1, acc0[n]);
        UNPACK_F32X2(f2, f3, acc1[n]);
        __half2 h0 = __floats2half2_rn(f0, f1);
        __half2 h1 = __floats2half2_rn(f2, f3);
        uint2 hv;
        hv.x = *reinterpret_cast<unsigned*>(&h0);
        hv.y = *reinterpret_cast<unsigned*>(&h1);
        *reinterpret_cast<uint2*>(
            reinterpret_cast<char*>(zh) + (size_t)node * 64 + oq * 8) = hv;
    }

    if (blockIdx.x == 0) {
        if (tid == 0) g_idx64 = s_bad ? 0 : 1;
    }
}

// ---------------------------------------------------------------------------
// Edge kernel (R5 config -- measured optimum of this family, 51.1us):
// 8 lanes per edge, uint2 (8B = 4 fp16) gathers, 4 distinct z rows per
// gather warp-instruction. FOUR edges per thread (m + q*E/4), all index/val
// loads and all 8 gathers front-batched (MLP=8). Output: 1 STG.128 per lane
// per edge, coalesced, streaming.
// ---------------------------------------------------------------------------
__global__ __launch_bounds__(256)
void edge_kernel(const __half2* __restrict__ zh,
                 const int* __restrict__ rows,
                 const int* __restrict__ cols,
                 const float* __restrict__ vals,
                 float4* __restrict__ out,
                 int n_edges) {
    int gid = blockIdx.x * blockDim.x + threadIdx.x;
    int E4 = (n_edges + 3) >> 2;
    int m = gid >> 3;
    int c = gid & 7;
    if (m >= E4) return;

    int sh = g_idx64;           // 0: int32 layout, 1: int64 (read low word)

    int e[4];
    bool has[4];
    #pragma unroll
    for (int q = 0; q < 4; q++) {
        e[q] = m + q * E4;
        has[q] = (e[q] < n_edges);
    }

    int ri[4], ci[4];
    float wv[4];
    #pragma unroll
    for (int q = 0; q < 4; q++) {
        ri[q] = 0; ci[q] = 0; wv[q] = 0.f;
        if (has[q]) {
            ri[q] = __ldcs(&rows[e[q] << sh]);
            ci[q] = __ldcs(&cols[e[q] << sh]);
            wv[q] = __ldcs(&vals[e[q]]);
        }
    }

    const uint2* zb = reinterpret_cast<const uint2*>(zh);   // 8 uint2 per row
    uint2 ga[4], gd[4];
    #pragma unroll
    for (int q = 0; q < 4; q++) {
        ga[q] = make_uint2(0, 0);
        gd[q] = make_uint2(0, 0);
        if (has[q]) {
            ga[q] = __ldg(&zb[(size_t)ri[q] * 8 + c]);
            gd[q] = __ldg(&zb[(size_t)ci[q] * 8 + c]);
        }
    }

    #pragma unroll
    for (int q = 0; q < 4; q++) {
        if (!has[q]) continue;
        float2 fa0 = __half22float2(*reinterpret_cast<__half2*>(&ga[q].x));
        float2 fd0 = __half22float2(*reinterpret_cast<__half2*>(&gd[q].x));
        float2 fa1 = __half22float2(*reinterpret_cast<__half2*>(&ga[q].y));
        float2 fd1 = __half22float2(*reinterpret_cast<__half2*>(&gd[q].y));
        float4 o;
        o.x = wv[q] * (fa0.x + fd0.x);
        o.y = wv[q] * (fa0.y + fd0.y);
        o.z = wv[q] * (fa1.x + fd1.x);
        o.w = wv[q] * (fa1.y + fd1.y);
        __stcs(&out[(size_t)e[q] * 8 + c], o);
    }
}

// ---------------------------------------------------------------------------
// Launch. Inputs (metadata order): x, W, b, edge_rows, edge_cols, edge_vals.
// ---------------------------------------------------------------------------
extern "C" void kernel_launch(void* const* d_in, const int* in_sizes, int n_in,
                              void* d_out, int out_size) {
    const float4* x4   = (const float4*)d_in[0];
    const float*  W    = (const float*)d_in[1];
    const float*  b    = (const float*)d_in[2];
    const void*   rows = d_in[3];
    const void*   cols = d_in[4];
    const float*  vals = (const float*)d_in[5];
    float4* out = (float4*)d_out;

    int n_nodes = in_sizes[0] / IN_F;
    int n_edges = in_sizes[3];

    __half2* zh = nullptr;
    cudaGetSymbolAddress((void**)&zh, g_zh);

    // 1) z = x @ W + b  (+ index-dtype probe in block 0)
    int gemm_blocks = (n_nodes + NPB - 1) / NPB;
    gemm_kernel<<<gemm_blocks, GEMM_BLOCK>>>(
        x4, W, b, zh, n_nodes, (const long long*)rows);

    // 2) out[e] = w_e * (z[r] + z[c]), 4 edges/thread, 8 lanes/edge
    int E4 = (n_edges + 3) >> 2;
    long long total = (long long)E4 * 8;
    int edge_blocks = (int)((total + 255) / 256);
    edge_kernel<<<edge_blocks, 256>>>(zh, (const int*)rows, (const int*)cols,
                                      vals, out, n_edges);
}

// round 8
// speedup vs baseline: 1.2893x; 1.1690x over previous
#include <cuda_runtime.h>
#include <cuda_fp16.h>
#include <cstdint>

// ---------------------------------------------------------------------------
// EdgeDense: z = x @ W + b  (N x 32, stored fp16), then
//            out[e] = w_e * (z[rows[e]] + z[cols[e]])   (fp32 out)
// N_NODES = 100000, IN = 128, OUT = 32, E = 1.6M
// GEMM via tf32 mma.sync (z^T tiles), edge kernel gather/scatter.
// ---------------------------------------------------------------------------

#define MAX_NODES 100000
#define IN_F 128
#define OUT_F 32

#define GB 256                  // gemm threads per block
#define NPB 256                 // nodes per block (32 per warp)
#define SXS 36                  // x staging stride (floats): conflict-free
#define ZTS 40                  // epilogue z tile stride (halves): 80B rows

// z in fp16: 100000 * 32 * 2B = 6.4 MB (L2-resident). Device global.
__device__ __half2 g_zh[(size_t)MAX_NODES * (OUT_F / 2)];
// Index-dtype flag: 1 => indices are int64, 0 => indices are int32.
__device__ int g_idx64;

#define CVT_TF32(u, f) \
    asm("cvt.rna.tf32.f32 %0, %1;" : "=r"(u) : "f"(f))

// D(16x8,f32) += A(16x8,tf32,row) * B(8x8,tf32,col)
#define MMA_TF32(d, a, b0, b1) \
    asm("mma.sync.aligned.m16n8k8.row.col.f32.tf32.tf32.f32 " \
        "{%0,%1,%2,%3}, {%4,%5,%6,%7}, {%8,%9}, {%0,%1,%2,%3};" \
        : "+f"((d)[0]), "+f"((d)[1]), "+f"((d)[2]), "+f"((d)[3]) \
        : "r"((a)[0]), "r"((a)[1]), "r"((a)[2]), "r"((a)[3]), \
          "r"(b0), "r"(b1))

// ---------------------------------------------------------------------------
// GEMM: computes z^T = W^T(32x128) @ x^T(128xN) with m16n8k8 tf32 MMA.
//   A = W^T : M=32 (2 m-tiles), K=128 (16 k-tiles). Fragments prebuilt in
//       smem (sWf) in exact per-lane order -> one LDS.128 per (mt,kt).
//   B = x^T col-major == x[node][k] row-major: staged per 32-k chunk in sx
//       (stride 36, conflict-free: bank = 4g+t distinct across the warp),
//       cvt.rna.tf32 applied at staging (RZ truncation would bias ~2^-10).
//   D = z^T[o][node]: warp covers 32 outputs x 32 nodes (2 mt x 4 nt tiles).
// Fragment maps (PTX m16n8k8 tf32; g=lane>>2, t=lane&3):
//   a0=A[g][t]  a1=A[g+8][t]  a2=A[g][t+4]  a3=A[g+8][t+4]
//   b0=B[t][g]  b1=B[t+4][g]
//   d0=D[g][2t] d1=D[g][2t+1] d2=D[g+8][2t] d3=D[g+8][2t+1]
// Epilogue: bias add, fp16 convert, stage through smem (sx reused) for
// coalesced 16B stores. Block 0 also runs the edge-index dtype probe
// (JAX x64-off hazard: int32 read as int64 words is >= 2^32 whenever the
// odd word != 0 -- unambiguous over 256 uniform indices in [0, 100000)).
// ---------------------------------------------------------------------------
__global__ __launch_bounds__(GB, 2)
void gemm_kernel(const float4* __restrict__ x4,
                 const float*  __restrict__ W,    // [128][32] row-major
                 const float*  __restrict__ b,    // [32]
                 __half2* __restrict__ zh,
                 int n_nodes,
                 const long long* __restrict__ idx_probe) {
    __shared__ unsigned sWf[2 * 16 * 32 * 4];     // 16 KB A fragments (tf32)
    __shared__ float sx[NPB * SXS];               // 36 KB x chunk / epilogue
    __shared__ int s_bad;

    int tid = threadIdx.x;
    int lane = tid & 31, wp = tid >> 5;
    int g = lane >> 2, t = lane & 3;
    int base = blockIdx.x * NPB;

    // Build A fragments: sWf[((mt*16+kt)*32+lane)*4 + r]
    for (int idx = tid; idx < 2 * 16 * 32; idx += GB) {
        int mt = idx >> 9;
        int rem = idx & 511;
        int kt = rem >> 5;
        int ln = rem & 31;
        int gg = ln >> 2, tt = ln & 3;
        int k0 = kt * 8, ob = mt * 16;
        float r0 = W[(k0 + tt) * OUT_F + ob + gg];
        float r1 = W[(k0 + tt) * OUT_F + ob + gg + 8];
        float r2 = W[(k0 + tt + 4) * OUT_F + ob + gg];
        float r3 = W[(k0 + tt + 4) * OUT_F + ob + gg + 8];
        unsigned u0, u1, u2, u3;
        CVT_TF32(u0, r0); CVT_TF32(u1, r1);
        CVT_TF32(u2, r2); CVT_TF32(u3, r3);
        *reinterpret_cast<uint4*>(&sWf[idx * 4]) = make_uint4(u0, u1, u2, u3);
    }
    if (blockIdx.x == 0 && tid == 0) s_bad = 0;

    if (blockIdx.x == 0) {
        long long v = idx_probe[tid];
        if (v < 0 || v >= (long long)n_nodes) atomicOr(&s_bad, 1);
    }

    // Staging geometry (fixed per thread): 8 float4 per chunk.
    int sn[8], sq[8], sgn[8];
    #pragma unroll
    for (int j = 0; j < 8; j++) {
        int i = j * GB + tid;
        sn[j] = i >> 3;                 // node 0..255
        sq[j] = i & 7;                  // float4 slot within 32-k chunk
        sgn[j] = base + sn[j];
    }

    // Prefetch chunk 0.
    float4 ld[8];
    #pragma unroll
    for (int j = 0; j < 8; j++) {
        ld[j] = make_float4(0.f, 0.f, 0.f, 0.f);
        if (sgn[j] < n_nodes)
            ld[j] = __ldg(&x4[(size_t)sgn[j] * (IN_F / 4) + sq[j]]);
    }

    float d[2][4][4];
    #pragma unroll
    for (int mt = 0; mt < 2; mt++)
        #pragma unroll
        for (int nt = 0; nt < 4; nt++)
            #pragma unroll
            for (int r = 0; r < 4; r++) d[mt][nt][r] = 0.f;

    unsigned* sxb = reinterpret_cast<unsigned*>(sx);

    #pragma unroll
    for (int c = 0; c < 4; c++) {
        // Scatter prefetched chunk (tf32-converted) into sx[node][k].
        #pragma unroll
        for (int j = 0; j < 8; j++) {
            unsigned u0, u1, u2, u3;
            CVT_TF32(u0, ld[j].x); CVT_TF32(u1, ld[j].y);
            CVT_TF32(u2, ld[j].z); CVT_TF32(u3, ld[j].w);
            *reinterpret_cast<uint4*>(&sxb[sn[j] * SXS + sq[j] * 4]) =
                make_uint4(u0, u1, u2, u3);
        }
        __syncthreads();

        // Prefetch next chunk (completes under the MMAs below).
        if (c < 3) {
            #pragma unroll
            for (int j = 0; j < 8; j++) {
                ld[j] = make_float4(0.f, 0.f, 0.f, 0.f);
                if (sgn[j] < n_nodes)
                    ld[j] = __ldg(&x4[(size_t)sgn[j] * (IN_F / 4)
                                      + (c + 1) * 8 + sq[j]]);
            }
        }

        // Load this chunk's A fragments (one LDS.128 each, conflict-free).
        unsigned a[2][4][4];
        #pragma unroll
        for (int mt = 0; mt < 2; mt++)
            #pragma unroll
            for (int kt = 0; kt < 4; kt++)
                *reinterpret_cast<uint4*>(a[mt][kt]) =
                    *reinterpret_cast<const uint4*>(
                        &sWf[((mt * 16 + c * 4 + kt) * 32 + lane) * 4]);

        #pragma unroll
        for (int nt = 0; nt < 4; nt++) {
            int nl = wp * 32 + nt * 8 + g;
            #pragma unroll
            for (int kt = 0; kt < 4; kt++) {
                unsigned b0 = sxb[nl * SXS + kt * 8 + t];
                unsigned b1 = sxb[nl * SXS + kt * 8 + t + 4];
                MMA_TF32(d[0][nt], a[0][kt], b0, b1);
                MMA_TF32(d[1][nt], a[1][kt], b0, b1);
            }
        }
        __syncthreads();   // compute done before next scatter reuses sx
    }

    // Epilogue: bias + fp16, stage via smem (sx reused as half zt[256][40]).
    float bias_v[4];
    bias_v[0] = __ldg(&b[g]);
    bias_v[1] = __ldg(&b[g + 8]);
    bias_v[2] = __ldg(&b[16 + g]);
    bias_v[3] = __ldg(&b[16 + g + 8]);

    __half* zt = reinterpret_cast<__half*>(sx);
    #pragma unroll
    for (int mt = 0; mt < 2; mt++) {
        #pragma unroll
        for (int nt = 0; nt < 4; nt++) {
            int n0 = wp * 32 + nt * 8 + 2 * t;
            int o0 = mt * 16 + g;
            zt[n0 * ZTS + o0]           = __float2half(d[mt][nt][0] + bias_v[mt * 2]);
            zt[(n0 + 1) * ZTS + o0]     = __float2half(d[mt][nt][1] + bias_v[mt * 2]);
            zt[n0 * ZTS + o0 + 8]       = __float2half(d[mt][nt][2] + bias_v[mt * 2 + 1]);
            zt[(n0 + 1) * ZTS + o0 + 8] = __float2half(d[mt][nt][3] + bias_v[mt * 2 + 1]);
        }
    }
    __syncwarp();

    // Coalesced store: warp writes its 32 nodes x 64B (4 x 16B per node).
    #pragma unroll
    for (int p = 0; p < 4; p++) {
        int i = p * 32 + lane;          // 0..127
        int nl = wp * 32 + (i >> 2);
        int part = i & 3;
        int node = base + nl;
        if (node < n_nodes) {
            uint4 v = *reinterpret_cast<const uint4*>(&zt[nl * ZTS + part * 8]);
            *reinterpret_cast<uint4*>(
                reinterpret_cast<char*>(zh) + (size_t)node * 64 + part * 16) = v;
        }
    }

    if (blockIdx.x == 0) {
        __syncthreads();
        if (tid == 0) g_idx64 = s_bad ? 0 : 1;
    }
}

// ---------------------------------------------------------------------------
// Edge kernel: 8 lanes per edge, uint2 (8B = 4 fp16) gathers (measured
// optimum: 4 distinct z rows per gather warp-instruction). FOUR CONSECUTIVE
// edges per thread so all index/val loads vectorize: rows/cols = 1 LDG.128
// (int32) or 2 (int64, picking low words .x/.z), vals = 1 LDG.128 -- was 12
// scalar LDGs. Fast path has zero per-edge predicates (tail guarded).
// Gathers front-batched (MLP=8). Stores: 1 STG.128 per lane per edge.
// ---------------------------------------------------------------------------
__global__ __launch_bounds__(256)
void edge_kernel(const __half2* __restrict__ zh,
                 const void* __restrict__ rows_raw,
                 const void* __restrict__ cols_raw,
                 const float* __restrict__ vals,
                 float4* __restrict__ out,
                 int n_edges) {
    int gid = blockIdx.x * blockDim.x + threadIdx.x;
    int m = gid >> 3;
    int c = gid & 7;
    int eb = m * 4;
    if (eb >= n_edges) return;

    int r[4], cc[4];
    float w[4];

    if (eb + 3 < n_edges) {
        // Vector index loads.
        if (g_idx64) {
            const int4* rp = (const int4*)rows_raw;
            const int4* cp = (const int4*)cols_raw;
            int4 ra = __ldcs(&rp[2 * m]), rb = __ldcs(&rp[2 * m + 1]);
            int4 ca = __ldcs(&cp[2 * m]), cb = __ldcs(&cp[2 * m + 1]);
            r[0] = ra.x; r[1] = ra.z; r[2] = rb.x; r[3] = rb.z;
            cc[0] = ca.x; cc[1] = ca.z; cc[2] = cb.x; cc[3] = cb.z;
        } else {
            int4 ra = __ldcs(&((const int4*)rows_raw)[m]);
            int4 ca = __ldcs(&((const int4*)cols_raw)[m]);
            r[0] = ra.x; r[1] = ra.y; r[2] = ra.z; r[3] = ra.w;
            cc[0] = ca.x; cc[1] = ca.y; cc[2] = ca.z; cc[3] = ca.w;
        }
        float4 wv = __ldcs(&((const float4*)vals)[m]);
        w[0] = wv.x; w[1] = wv.y; w[2] = wv.z; w[3] = wv.w;

        const uint2* zb = reinterpret_cast<const uint2*>(zh);
        uint2 ga[4], gd[4];
        #pragma unroll
        for (int q = 0; q < 4; q++) {
            ga[q] = __ldg(&zb[(size_t)r[q] * 8 + c]);
            gd[q] = __ldg(&zb[(size_t)cc[q] * 8 + c]);
        }

        #pragma unroll
        for (int q = 0; q < 4; q++) {
            float2 fa0 = __half22float2(*reinterpret_cast<__half2*>(&ga[q].x));
            float2 fd0 = __half22float2(*reinterpret_cast<__half2*>(&gd[q].x));
            float2 fa1 = __half22float2(*reinterpret_cast<__half2*>(&ga[q].y));
            float2 fd1 = __half22float2(*reinterpret_cast<__half2*>(&gd[q].y));
            float4 o;
            o.x = w[q] * (fa0.x + fd0.x);
            o.y = w[q] * (fa0.y + fd0.y);
            o.z = w[q] * (fa1.x + fd1.x);
            o.w = w[q] * (fa1.y + fd1.y);
            __stcs(&out[(size_t)(eb + q) * 8 + c], o);
        }
    } else {
        // Tail: per-edge guarded scalar path.
        int sh = g_idx64;
        const int* rp = (const int*)rows_raw;
        const int* cp = (const int*)cols_raw;
        for (int q = 0; q < 4; q++) {
            int e = eb + q;
            if (e >= n_edges) break;
            int rr = __ldcs(&rp[e << sh]);
            int cl = __ldcs(&cp[e << sh]);
            float ww = __ldcs(&vals[e]);
            const uint2* zb = reinterpret_cast<const uint2*>(zh);
            uint2 a = __ldg(&zb[(size_t)rr * 8 + c]);
            uint2 dd = __ldg(&zb[(size_t)cl * 8 + c]);
            float2 fa0 = __half22float2(*reinterpret_cast<__half2*>(&a.x));
            float2 fd0 = __half22float2(*reinterpret_cast<__half2*>(&dd.x));
            float2 fa1 = __half22float2(*reinterpret_cast<__half2*>(&a.y));
            float2 fd1 = __half22float2(*reinterpret_cast<__half2*>(&dd.y));
            float4 o;
            o.x = ww * (fa0.x + fd0.x);
            o.y = ww * (fa0.y + fd0.y);
            o.z = ww * (fa1.x + fd1.x);
            o.w = ww * (fa1.y + fd1.y);
            __stcs(&out[(size_t)e * 8 + c], o);
        }
    }
}

// ---------------------------------------------------------------------------
// Launch. Inputs (metadata order): x, W, b, edge_rows, edge_cols, edge_vals.
// ---------------------------------------------------------------------------
extern "C" void kernel_launch(void* const* d_in, const int* in_sizes, int n_in,
                              void* d_out, int out_size) {
    const float4* x4   = (const float4*)d_in[0];
    const float*  W    = (const float*)d_in[1];
    const float*  b    = (const float*)d_in[2];
    const void*   rows = d_in[3];
    const void*   cols = d_in[4];
    const float*  vals = (const float*)d_in[5];
    float4* out = (float4*)d_out;

    int n_nodes = in_sizes[0] / IN_F;
    int n_edges = in_sizes[3];

    __half2* zh = nullptr;
    cudaGetSymbolAddress((void**)&zh, g_zh);

    // 1) z = x @ W + b via tf32 MMA (+ index-dtype probe in block 0)
    int gemm_blocks = (n_nodes + NPB - 1) / NPB;
    gemm_kernel<<<gemm_blocks, GB>>>(
        x4, W, b, zh, n_nodes, (const long long*)rows);

    // 2) out[e] = w_e * (z[r] + z[c]), 4 consecutive edges/thread, 8 lanes/edge
    int M = (n_edges + 3) >> 2;
    long long total = (long long)M * 8;
    int edge_blocks = (int)((total + 255) / 256);
    edge_kernel<<<edge_blocks, 256>>>(zh, rows, cols, vals, out, n_edges);
}